// round 5
// baseline (speedup 1.0000x reference)
#include <cuda_runtime.h>
#include <math.h>

// Problem constants (fixed by the reference)
#define S_SZ 4096
#define D_SZ 300
#define C_SZ 4
#define D4   75             // float4 per embedding row
#define NB   128            // blocks per kernel
#define RPB  32             // rows per gather block
#define NTA  512            // threads, gather kernels
#define NTB  256            // threads, scores kernel

// Scratch (device globals; no allocation allowed)
__device__ float    g_part1[D_SZ * NB];   // transposed: [d][b]
__device__ float    g_part2[D_SZ * NB];   // transposed: [d][b]
__device__ float    g_mid[D_SZ];
__device__ float    g_t[D_SZ];
__device__ float    g_scores[S_SZ];
__device__ float    g_reward[S_SZ];
__device__ float    g_sink;
__device__ unsigned g_cnt1 = 0, g_cnt2 = 0, g_cnt3 = 0;

__device__ __forceinline__ float warp_sum(float p) {
    #pragma unroll
    for (int o = 16; o > 0; o >>= 1) p += __shfl_xor_sync(0xFFFFFFFFu, p, o);
    return p;
}
__device__ __forceinline__ float warp_max(float p) {
    #pragma unroll
    for (int o = 16; o > 0; o >>= 1) p = fmaxf(p, __shfl_xor_sync(0xFFFFFFFFu, p, o));
    return p;
}

// Last-block-done: true in exactly one block after all NB blocks' stores are
// visible. Counter self-resets -> graph-replay safe.
__device__ __forceinline__ bool last_block(unsigned* cnt, bool* s_last) {
    __threadfence();
    __syncthreads();
    if (threadIdx.x == 0)
        *s_last = (atomicAdd(cnt, 1u) == NB - 1);
    __syncthreads();
    if (*s_last) {
        __threadfence();
        if (threadIdx.x == 0) *cnt = 0;
        return true;
    }
    return false;
}

// y = W_row . v (both 300 floats), float4 loads, 4 accumulator chains,
// 5 loads per step in flight. Fixed order -> deterministic.
__device__ __forceinline__ float dot300(const float4* __restrict__ wr,
                                        const float4* __restrict__ v4) {
    float a0 = 0, a1 = 0, a2 = 0, a3 = 0;
    #pragma unroll 3
    for (int i = 0; i < D4; i += 5) {
        float4 w0 = __ldg(&wr[i+0]), w1 = __ldg(&wr[i+1]), w2 = __ldg(&wr[i+2]);
        float4 w3 = __ldg(&wr[i+3]), w4 = __ldg(&wr[i+4]);
        float4 u0 = v4[i+0], u1 = v4[i+1], u2 = v4[i+2], u3 = v4[i+3], u4 = v4[i+4];
        a0 = fmaf(w0.x, u0.x, a0); a1 = fmaf(w0.y, u0.y, a1);
        a2 = fmaf(w0.z, u0.z, a2); a3 = fmaf(w0.w, u0.w, a3);
        a0 = fmaf(w1.x, u1.x, a0); a1 = fmaf(w1.y, u1.y, a1);
        a2 = fmaf(w1.z, u1.z, a2); a3 = fmaf(w1.w, u1.w, a3);
        a0 = fmaf(w2.x, u2.x, a0); a1 = fmaf(w2.y, u2.y, a1);
        a2 = fmaf(w2.z, u2.z, a2); a3 = fmaf(w2.w, u2.w, a3);
        a0 = fmaf(w3.x, u3.x, a0); a1 = fmaf(w3.y, u3.y, a1);
        a2 = fmaf(w3.z, u3.z, a2); a3 = fmaf(w3.w, u3.w, a3);
        a0 = fmaf(w4.x, u4.x, a0); a1 = fmaf(w4.y, u4.y, a1);
        a2 = fmaf(w4.z, u4.z, a2); a3 = fmaf(w4.w, u4.w, a3);
    }
    return (a0 + a1) + (a2 + a3);
}

// ---------------------------------------------------------------------------
// K_A: float4 gather -> transposed partials; idle threads prefetch W1/Wb to
// L2; last block: dense (coalesced warp-per-d), mid = W1*dense+b1, t = Wb*mid
// ---------------------------------------------------------------------------
__global__ __launch_bounds__(NTA)
void k_gather_mlp(const int* __restrict__ x, const float* __restrict__ emb,
                  const float* __restrict__ W1, const float* __restrict__ b1,
                  const float* __restrict__ Wb)
{
    __shared__ int    s_idx[RPB];
    __shared__ bool   s_last;
    __shared__ float4 s_acc[4][D4];
    __shared__ float4 s_dense4[D4];
    __shared__ float4 s_mid4[D4];

    const int b = blockIdx.x, tid = threadIdx.x;
    const int lane = tid & 31, w = tid >> 5;

    if (tid < RPB) s_idx[tid] = __ldg(&x[b * RPB + tid]);
    __syncthreads();

    const float4* emb4 = (const float4*)emb;
    if (tid < D_SZ) {
        const int c = tid % D4, g = tid / D4;   // col, row-group
        float4 acc = make_float4(0.f, 0.f, 0.f, 0.f);
        #pragma unroll
        for (int k = 0; k < 8; k++) {
            float4 v = __ldg(&emb4[(long)s_idx[g * 8 + k] * D4 + c]);
            acc.x += v.x; acc.y += v.y; acc.z += v.z; acc.w += v.w;
        }
        s_acc[g][c] = acc;
    } else {
        // prefetch W1/Wb into L2 (22500 float4 each, spread over blocks)
        const int p = tid - D_SZ;               // 0..211
        const int i = b * 212 + p;
        if (i < 22500) {
            float4 a = __ldg(&((const float4*)W1)[i]);
            float4 c = __ldg(&((const float4*)Wb)[i]);
            float s = a.x + c.w;
            if (s != s) g_sink = s;             // keep loads alive; never fires
        }
    }
    __syncthreads();
    if (tid < D4) {
        float4 t0 = s_acc[0][tid], t1 = s_acc[1][tid];
        float4 t2 = s_acc[2][tid], t3 = s_acc[3][tid];
        g_part1[(4 * tid + 0) * NB + b] = (t0.x + t1.x) + (t2.x + t3.x);
        g_part1[(4 * tid + 1) * NB + b] = (t0.y + t1.y) + (t2.y + t3.y);
        g_part1[(4 * tid + 2) * NB + b] = (t0.z + t1.z) + (t2.z + t3.z);
        g_part1[(4 * tid + 3) * NB + b] = (t0.w + t1.w) + (t2.w + t3.w);
    }

    if (!last_block(&g_cnt1, &s_last)) return;

    // ---- dense: coalesced warp-per-d reduce of 128 partials ----
    float* sd = (float*)s_dense4;
    for (int d = w; d < D_SZ; d += 16) {
        const float* pp = g_part1 + (long)d * NB;
        float v = (pp[lane] + pp[lane + 32]) + (pp[lane + 64] + pp[lane + 96]);
        v = warp_sum(v);
        if (lane == 0) sd[d] = v * (1.0f / S_SZ);
    }
    __syncthreads();
    // ---- mid = W1*dense + b1 (W1 L2-warm from prefetch) ----
    float* sm = (float*)s_mid4;
    if (tid < D_SZ) {
        float m = dot300((const float4*)(W1 + (long)tid * D_SZ), s_dense4) + __ldg(&b1[tid]);
        sm[tid]    = m;
        g_mid[tid] = m;
    }
    __syncthreads();
    // ---- t = Wb*mid ----
    if (tid < D_SZ)
        g_t[tid] = dot300((const float4*)(Wb + (long)tid * D_SZ), s_mid4);
}

// ---------------------------------------------------------------------------
// K_B: scores via warp-per-row float4 dots (emb L2-warm); last block: softmax
// ---------------------------------------------------------------------------
__global__ __launch_bounds__(NTB)
void k_scores_softmax(const int* __restrict__ x, const float* __restrict__ emb,
                      const float* __restrict__ bb, float* __restrict__ reward_out)
{
    __shared__ float4 s_t4[D4];
    __shared__ bool   s_last;
    __shared__ float  s_red[NTB / 32];
    __shared__ float  s_bc;

    const int tid = threadIdx.x, lane = tid & 31, w = tid >> 5;
    float* st = (float*)s_t4;
    for (int d = tid; d < D_SZ; d += NTB) st[d] = g_t[d];   // FIX: strided fill
    __syncthreads();

    const float bias = __ldg(bb);
    const float4* emb4 = (const float4*)emb;
    const int gw = (blockIdx.x * NTB + tid) >> 5;

    for (int s = gw; s < S_SZ; s += (NB * NTB) >> 5) {
        const float4* row = emb4 + (long)__ldg(&x[s]) * D4;
        float4 u0 = __ldg(&row[lane]);
        float4 u1 = __ldg(&row[lane + 32]);
        float4 t0 = s_t4[lane], t1 = s_t4[lane + 32];
        float p = 0.f;
        p = fmaf(u0.x, t0.x, p); p = fmaf(u0.y, t0.y, p);
        p = fmaf(u0.z, t0.z, p); p = fmaf(u0.w, t0.w, p);
        p = fmaf(u1.x, t1.x, p); p = fmaf(u1.y, t1.y, p);
        p = fmaf(u1.z, t1.z, p); p = fmaf(u1.w, t1.w, p);
        if (lane < D4 - 64) {                       // last 11 float4
            float4 u2 = __ldg(&row[lane + 64]);
            float4 t2 = s_t4[lane + 64];
            p = fmaf(u2.x, t2.x, p); p = fmaf(u2.y, t2.y, p);
            p = fmaf(u2.z, t2.z, p); p = fmaf(u2.w, t2.w, p);
        }
        p = warp_sum(p);
        if (lane == 0) g_scores[s] = p + bias;
    }

    if (!last_block(&g_cnt2, &s_last)) return;

    // ---- softmax over 4096 (fixed order) ----
    float mx = -3.4e38f;
    for (int s = tid; s < S_SZ; s += NTB) mx = fmaxf(mx, g_scores[s]);
    mx = warp_max(mx);
    if (lane == 0) s_red[w] = mx;
    __syncthreads();
    float bm = (lane < NTB / 32) ? s_red[lane] : -3.4e38f;
    bm = warp_max(bm);
    if (tid == 0) s_bc = bm;
    __syncthreads();
    bm = s_bc;

    float es = 0.f;
    for (int s = tid; s < S_SZ; s += NTB) es += expf(g_scores[s] - bm);
    es = warp_sum(es);
    __syncthreads();
    if (lane == 0) s_red[w] = es;
    __syncthreads();
    float bs = (lane < NTB / 32) ? s_red[lane] : 0.f;
    bs = warp_sum(bs);
    if (tid == 0) s_bc = 1.0f / bs;
    __syncthreads();
    const float inv = s_bc;

    for (int s = tid; s < S_SZ; s += NTB) {
        float r = expf(g_scores[s] - bm) * inv;
        reward_out[s] = r;
        g_reward[s]   = r;
    }
}

// ---------------------------------------------------------------------------
// K_C: weighted float4 gather (L2-warm); last block: addition + output logits
// ---------------------------------------------------------------------------
__global__ __launch_bounds__(NTA)
void k_weighted_final(const int* __restrict__ x, const float* __restrict__ emb,
                      const float* __restrict__ W2, const float* __restrict__ b2,
                      float* __restrict__ out)
{
    __shared__ int    s_idx[RPB];
    __shared__ float  s_wt[RPB];
    __shared__ bool   s_last;
    __shared__ float4 s_acc[4][D4];
    __shared__ float4 s_vec4[D4];

    const int b = blockIdx.x, tid = threadIdx.x;
    const int lane = tid & 31, w = tid >> 5;

    if (tid < RPB) {
        s_idx[tid] = __ldg(&x[b * RPB + tid]);
        s_wt[tid]  = g_reward[b * RPB + tid];
    }
    __syncthreads();

    const float4* emb4 = (const float4*)emb;
    if (tid < D_SZ) {
        const int c = tid % D4, g = tid / D4;
        float4 acc = make_float4(0.f, 0.f, 0.f, 0.f);
        #pragma unroll
        for (int k = 0; k < 8; k++) {
            const int r = g * 8 + k;
            const float wt = s_wt[r];
            float4 v = __ldg(&emb4[(long)s_idx[r] * D4 + c]);
            acc.x = fmaf(wt, v.x, acc.x); acc.y = fmaf(wt, v.y, acc.y);
            acc.z = fmaf(wt, v.z, acc.z); acc.w = fmaf(wt, v.w, acc.w);
        }
        s_acc[g][c] = acc;
    }
    __syncthreads();
    if (tid < D4) {
        float4 t0 = s_acc[0][tid], t1 = s_acc[1][tid];
        float4 t2 = s_acc[2][tid], t3 = s_acc[3][tid];
        g_part2[(4 * tid + 0) * NB + b] = (t0.x + t1.x) + (t2.x + t3.x);
        g_part2[(4 * tid + 1) * NB + b] = (t0.y + t1.y) + (t2.y + t3.y);
        g_part2[(4 * tid + 2) * NB + b] = (t0.z + t1.z) + (t2.z + t3.z);
        g_part2[(4 * tid + 3) * NB + b] = (t0.w + t1.w) + (t2.w + t3.w);
    }

    if (!last_block(&g_cnt3, &s_last)) return;

    // ---- addition + mid ----
    float* sv = (float*)s_vec4;
    for (int d = w; d < D_SZ; d += 16) {
        const float* pp = g_part2 + (long)d * NB;
        float v = (pp[lane] + pp[lane + 32]) + (pp[lane + 64] + pp[lane + 96]);
        v = warp_sum(v);
        if (lane == 0) sv[d] = g_mid[d] + v * (1.0f / S_SZ);
    }
    __syncthreads();

    // ---- 4 output dots ----
    if (w < C_SZ) {
        const float* wr = W2 + (long)w * D_SZ;
        float p = 0.f;
        #pragma unroll 10
        for (int e = lane; e < D_SZ; e += 32) p = fmaf(__ldg(&wr[e]), sv[e], p);
        p = warp_sum(p);
        if (lane == 0) out[w] = p + __ldg(&b2[w]);
    }
}

// ---------------------------------------------------------------------------
extern "C" void kernel_launch(void* const* d_in, const int* in_sizes, int n_in,
                              void* d_out, int out_size)
{
    const int*   x   = (const int*)  d_in[0];
    const float* emb = (const float*)d_in[1];
    const float* W1  = (const float*)d_in[2];
    const float* b1  = (const float*)d_in[3];
    const float* Wb  = (const float*)d_in[4];
    const float* bb  = (const float*)d_in[5];
    const float* W2  = (const float*)d_in[6];
    const float* b2  = (const float*)d_in[7];
    float* out = (float*)d_out;   // out[0:4] = output, out[4:4100] = reward

    k_gather_mlp<<<NB, NTA>>>(x, emb, W1, b1, Wb);
    k_scores_softmax<<<NB, NTB>>>(x, emb, bb, out + C_SZ);
    k_weighted_final<<<NB, NTA>>>(x, emb, W2, b2, out);
}

// round 6
// speedup vs baseline: 2.1135x; 2.1135x over previous
#include <cuda_runtime.h>
#include <math.h>

// Problem constants (fixed by the reference)
#define S_SZ  4096
#define D_SZ  300
#define C_SZ  4
#define D4    75            // float4 per embedding row
#define NB    128           // blocks (<= 148 SMs -> all resident)
#define RPB   32            // sequence rows per block
#define NT    512           // threads per block
#define NWARP 16

// Scratch (device globals; no allocation allowed)
__device__ float    g_part1[D_SZ * NB];   // transposed [d][b]
__device__ float    g_part2[D_SZ * NB];   // transposed [d][b]
__device__ float    g_dense[D_SZ];
__device__ float    g_mid[D_SZ];
__device__ float    g_t[D_SZ];
__device__ float    g_vec[D_SZ];
__device__ float    g_psum[NB];
__device__ float    g_sink;
__device__ unsigned g_cnt[8];             // zero-init; self-resetting
__device__ unsigned g_gen[8];             // monotonically increasing (replay-safe)

__device__ __forceinline__ float warp_sum(float p) {
    #pragma unroll
    for (int o = 16; o > 0; o >>= 1) p += __shfl_xor_sync(0xFFFFFFFFu, p, o);
    return p;
}

// Grid barrier #i (generation counter). Correct because each block arrives at
// barrier i exactly once per launch: gen can only flip after ALL NB arrivals,
// so no block can observe a flip before contributing. Count self-resets.
__device__ __forceinline__ void gbar(int i) {
    __syncthreads();
    if (threadIdx.x == 0) {
        __threadfence();                               // release
        unsigned g = ((volatile unsigned*)g_gen)[i];
        if (atomicAdd(&g_cnt[i], 1u) == NB - 1) {
            g_cnt[i] = 0;
            __threadfence();
            atomicAdd(&g_gen[i], 1u);                  // release all
        } else {
            while (((volatile unsigned*)g_gen)[i] == g) __nanosleep(32);
        }
        __threadfence();                               // acquire
    }
    __syncthreads();
}

__device__ __forceinline__ float dot4(float4 a, float4 b) {
    return fmaf(a.x, b.x, fmaf(a.y, b.y, fmaf(a.z, b.z, a.w * b.w)));
}

// Warp-collective dot of a 300-float global row with a 300-float smem vector.
// 75 float4 = lane + lane+32 + (lane+64 for lane<11). Fixed order.
__device__ __forceinline__ float warp_row_dot(const float4* __restrict__ row,
                                              const float4* __restrict__ sv4,
                                              int lane) {
    float p = dot4(__ldg(&row[lane]),      sv4[lane])
            + dot4(__ldg(&row[lane + 32]), sv4[lane + 32]);
    if (lane < D4 - 64)
        p += dot4(__ldg(&row[lane + 64]), sv4[lane + 64]);
    return warp_sum(p);
}

// ---------------------------------------------------------------------------
__global__ __launch_bounds__(NT)
void fused(const int* __restrict__ x, const float* __restrict__ emb,
           const float* __restrict__ W1, const float* __restrict__ b1,
           const float* __restrict__ Wb, const float* __restrict__ bb,
           const float* __restrict__ W2, const float* __restrict__ b2,
           float* __restrict__ out)
{
    const int b = blockIdx.x, tid = threadIdx.x;
    const int lane = tid & 31, w = tid >> 5;
    const int gw = b * NWARP + w;                      // global warp id

    __shared__ int    s_idx[RPB];
    __shared__ float4 s_acc[4][D4];
    __shared__ float4 s_v4[D4 + 1];
    __shared__ float  s_sc[RPB];
    __shared__ float  s_e[RPB];
    __shared__ float  s_wt[RPB];
    __shared__ float  s_bc;
    float* s_v = (float*)s_v4;

    if (tid < RPB) s_idx[tid] = __ldg(&x[b * RPB + tid]);
    __syncthreads();

    const float4* emb4 = (const float4*)emb;

    // ---- Phase A: gather this block's 32 rows (DRAM); spares prefetch W1/Wb
    if (tid < D_SZ) {
        const int c = tid % D4, g = tid / D4;
        float4 acc = make_float4(0.f, 0.f, 0.f, 0.f);
        #pragma unroll
        for (int k = 0; k < 8; k++) {
            float4 v = __ldg(&emb4[(long)s_idx[g * 8 + k] * D4 + c]);
            acc.x += v.x; acc.y += v.y; acc.z += v.z; acc.w += v.w;
        }
        s_acc[g][c] = acc;
    } else {
        const long i = (long)b * 212 + (tid - D_SZ);   // covers 22500 float4
        if (i < 22500) {
            float4 a = __ldg(&((const float4*)W1)[i]);
            float4 c = __ldg(&((const float4*)Wb)[i]);
            float s = a.x + c.w;
            if (s != s) g_sink = s;                    // keep loads; never fires
        }
    }
    __syncthreads();
    if (tid < D4) {
        float4 t0 = s_acc[0][tid], t1 = s_acc[1][tid];
        float4 t2 = s_acc[2][tid], t3 = s_acc[3][tid];
        g_part1[(4 * tid + 0) * NB + b] = (t0.x + t1.x) + (t2.x + t3.x);
        g_part1[(4 * tid + 1) * NB + b] = (t0.y + t1.y) + (t2.y + t3.y);
        g_part1[(4 * tid + 2) * NB + b] = (t0.z + t1.z) + (t2.z + t3.z);
        g_part1[(4 * tid + 3) * NB + b] = (t0.w + t1.w) + (t2.w + t3.w);
    }
    gbar(0);

    // ---- Phase B: dense[d] = sum_b part1[d][b] / S  (warp-per-d, parallel)
    if (gw < D_SZ) {
        const float* pp = g_part1 + (long)gw * NB;
        float v = (pp[lane] + pp[lane + 32]) + (pp[lane + 64] + pp[lane + 96]);
        v = warp_sum(v);
        if (lane == 0) g_dense[gw] = v * (1.0f / S_SZ);
    }
    gbar(1);

    // ---- Phase C: mid = W1*dense + b1 (warp-per-row across the grid)
    for (int d = tid; d < D_SZ; d += NT) s_v[d] = g_dense[d];
    __syncthreads();
    if (gw < D_SZ) {
        float p = warp_row_dot((const float4*)(W1 + (long)gw * D_SZ), s_v4, lane);
        if (lane == 0) g_mid[gw] = p + __ldg(&b1[gw]);
    }
    gbar(2);

    // ---- Phase D: t = Wb*mid
    for (int d = tid; d < D_SZ; d += NT) s_v[d] = g_mid[d];
    __syncthreads();
    if (gw < D_SZ) {
        float p = warp_row_dot((const float4*)(Wb + (long)gw * D_SZ), s_v4, lane);
        if (lane == 0) g_t[gw] = p;
    }
    gbar(3);

    // ---- Phase E: scores for this block's 32 rows + local exp partial sum.
    // Scores are tiny by construction (|s| << 1), so unshifted exp is exact-safe.
    for (int d = tid; d < D_SZ; d += NT) s_v[d] = g_t[d];
    __syncthreads();
    {
        const float bias = __ldg(bb);
        #pragma unroll
        for (int j = 0; j < 2; j++) {
            const int r = w * 2 + j;                   // 0..31
            float p = warp_row_dot(emb4 + (long)s_idx[r] * D4, s_v4, lane);
            if (lane == 0) s_sc[r] = p + bias;
        }
    }
    __syncthreads();
    if (w == 0) {
        float e = expf(s_sc[lane]);
        s_e[lane] = e;
        float ps = warp_sum(e);
        if (lane == 0) g_psum[b] = ps;
    }
    gbar(4);

    // ---- Phase F: global sum (identical order in every block), weights,
    //      reward output, weighted gather (emb L2-warm)
    if (w == 0) {
        float v = (g_psum[lane] + g_psum[lane + 32])
                + (g_psum[lane + 64] + g_psum[lane + 96]);
        v = warp_sum(v);
        if (lane == 0) s_bc = 1.0f / v;
    }
    __syncthreads();
    if (tid < RPB) {
        float wt = s_e[tid] * s_bc;
        s_wt[tid] = wt;
        out[C_SZ + b * RPB + tid] = wt;
    }
    __syncthreads();
    if (tid < D_SZ) {
        const int c = tid % D4, g = tid / D4;
        float4 acc = make_float4(0.f, 0.f, 0.f, 0.f);
        #pragma unroll
        for (int k = 0; k < 8; k++) {
            const int r = g * 8 + k;
            const float wt = s_wt[r];
            float4 v = __ldg(&emb4[(long)s_idx[r] * D4 + c]);
            acc.x = fmaf(wt, v.x, acc.x); acc.y = fmaf(wt, v.y, acc.y);
            acc.z = fmaf(wt, v.z, acc.z); acc.w = fmaf(wt, v.w, acc.w);
        }
        s_acc[g][c] = acc;
    }
    __syncthreads();
    if (tid < D4) {
        float4 t0 = s_acc[0][tid], t1 = s_acc[1][tid];
        float4 t2 = s_acc[2][tid], t3 = s_acc[3][tid];
        g_part2[(4 * tid + 0) * NB + b] = (t0.x + t1.x) + (t2.x + t3.x);
        g_part2[(4 * tid + 1) * NB + b] = (t0.y + t1.y) + (t2.y + t3.y);
        g_part2[(4 * tid + 2) * NB + b] = (t0.z + t1.z) + (t2.z + t3.z);
        g_part2[(4 * tid + 3) * NB + b] = (t0.w + t1.w) + (t2.w + t3.w);
    }
    gbar(5);

    // ---- Phase G: vec[d] = mid[d] + reduce(part2)/S  (warp-per-d)
    if (gw < D_SZ) {
        const float* pp = g_part2 + (long)gw * NB;
        float v = (pp[lane] + pp[lane + 32]) + (pp[lane + 64] + pp[lane + 96]);
        v = warp_sum(v);
        if (lane == 0) g_vec[gw] = g_mid[gw] + v * (1.0f / S_SZ);
    }
    gbar(6);

    // ---- Phase H: block 0 emits the 4 logits
    if (b == 0) {
        for (int d = tid; d < D_SZ; d += NT) s_v[d] = g_vec[d];
        __syncthreads();
        if (w < C_SZ) {
            float p = warp_row_dot((const float4*)(W2 + (long)w * D_SZ), s_v4, lane);
            if (lane == 0) out[w] = p + __ldg(&b2[w]);
        }
    }
}

// ---------------------------------------------------------------------------
extern "C" void kernel_launch(void* const* d_in, const int* in_sizes, int n_in,
                              void* d_out, int out_size)
{
    const int*   x   = (const int*)  d_in[0];
    const float* emb = (const float*)d_in[1];
    const float* W1  = (const float*)d_in[2];
    const float* b1  = (const float*)d_in[3];
    const float* Wb  = (const float*)d_in[4];
    const float* bb  = (const float*)d_in[5];
    const float* W2  = (const float*)d_in[6];
    const float* b2  = (const float*)d_in[7];
    float* out = (float*)d_out;   // out[0:4] = output, out[4:4100] = reward

    fused<<<NB, NT>>>(x, emb, W1, b1, Wb, bb, W2, b2, out);
}

// round 7
// speedup vs baseline: 3.0575x; 1.4467x over previous
#include <cuda_runtime.h>
#include <math.h>

// Problem constants (fixed by the reference)
#define S_SZ  4096
#define D_SZ  300
#define C_SZ  4
#define D4    75            // float4 per embedding row
#define NB    128           // blocks (fully resident)
#define RPB   32            // sequence rows per block
#define NT    512           // threads per block
#define NWARP 16

// Scratch (device globals; no allocation allowed)
__device__ float    g_part1[D_SZ * NB];   // transposed [d][b]
__device__ float    g_dense[D_SZ];
__device__ float    g_mid[D_SZ];
__device__ float    g_t[D_SZ];
__device__ float    g_w2mid[C_SZ];
__device__ float    g_psum[NB];           // per-block unnormalized exp sums
__device__ float    g_y[C_SZ * NB];       // per-block W2 . (unnorm weighted sum)
__device__ float    g_sink;
__device__ unsigned g_cnt[5];             // zero-init; self-resetting
__device__ unsigned g_gen[5];             // monotonic (graph-replay safe)

__device__ __forceinline__ float warp_sum(float p) {
    #pragma unroll
    for (int o = 16; o > 0; o >>= 1) p += __shfl_xor_sync(0xFFFFFFFFu, p, o);
    return p;
}

// Grid barrier #i. Arrival = acq_rel atomic (synchronizes with all earlier
// release-arrives); waiters spin on ld.acquire of the generation word.
// Each block arrives exactly once per launch; count self-resets before the
// gen bump, which is safe because no block can re-arrive until next launch.
__device__ __forceinline__ void gbar(int i) {
    __syncthreads();
    if (threadIdx.x == 0) {
        unsigned g;
        asm volatile("ld.relaxed.gpu.u32 %0,[%1];"
                     : "=r"(g) : "l"(&g_gen[i]) : "memory");
        unsigned old;
        asm volatile("atom.acq_rel.gpu.add.u32 %0,[%1],%2;"
                     : "=r"(old) : "l"(&g_cnt[i]), "r"(1u) : "memory");
        if (old == NB - 1) {
            asm volatile("st.relaxed.gpu.u32 [%0],%1;"
                         :: "l"(&g_cnt[i]), "r"(0u) : "memory");
            unsigned d;
            asm volatile("atom.acq_rel.gpu.add.u32 %0,[%1],%2;"
                         : "=r"(d) : "l"(&g_gen[i]), "r"(1u) : "memory");
        } else {
            unsigned cur;
            do {
                __nanosleep(32);
                asm volatile("ld.acquire.gpu.u32 %0,[%1];"
                             : "=r"(cur) : "l"(&g_gen[i]) : "memory");
            } while (cur == g);
        }
    }
    __syncthreads();
}

__device__ __forceinline__ float dot4(float4 a, float4 b) {
    return fmaf(a.x, b.x, fmaf(a.y, b.y, fmaf(a.z, b.z, a.w * b.w)));
}

// Warp-collective dot of a 300-float global row with a 300-float smem vector.
__device__ __forceinline__ float warp_row_dot(const float4* __restrict__ row,
                                              const float4* __restrict__ sv4,
                                              int lane) {
    float p = dot4(__ldg(&row[lane]),      sv4[lane])
            + dot4(__ldg(&row[lane + 32]), sv4[lane + 32]);
    if (lane < D4 - 64)
        p += dot4(__ldg(&row[lane + 64]), sv4[lane + 64]);
    return warp_sum(p);
}

// ---------------------------------------------------------------------------
__global__ __launch_bounds__(NT)
void fused(const int* __restrict__ x, const float* __restrict__ emb,
           const float* __restrict__ W1, const float* __restrict__ b1,
           const float* __restrict__ Wb, const float* __restrict__ bb,
           const float* __restrict__ W2, const float* __restrict__ b2,
           float* __restrict__ out)
{
    const int b = blockIdx.x, tid = threadIdx.x;
    const int lane = tid & 31, w = tid >> 5;

    __shared__ int    s_idx[RPB];
    __shared__ float4 s_acc[4][D4];
    __shared__ float4 s_v4[D4 + 1];
    __shared__ float  s_sc[RPB];
    __shared__ float  s_e[RPB];
    __shared__ float  s_bc;
    float* s_v = (float*)s_v4;

    if (tid < RPB) s_idx[tid] = __ldg(&x[b * RPB + tid]);
    __syncthreads();

    const float4* emb4 = (const float4*)emb;

    // ---- Phase A: gather this block's 32 rows (DRAM); spares prefetch W1/Wb/W2
    if (tid < D_SZ) {
        const int c = tid % D4, g = tid / D4;
        float4 acc = make_float4(0.f, 0.f, 0.f, 0.f);
        #pragma unroll
        for (int k = 0; k < 8; k++) {
            float4 v = __ldg(&emb4[(long)s_idx[g * 8 + k] * D4 + c]);
            acc.x += v.x; acc.y += v.y; acc.z += v.z; acc.w += v.w;
        }
        s_acc[g][c] = acc;
    } else {
        const long i = (long)b * 212 + (tid - D_SZ);   // covers 22500 float4
        if (i < 22500) {
            float4 a = __ldg(&((const float4*)W1)[i]);
            float4 c = __ldg(&((const float4*)Wb)[i]);
            float s = a.x + c.w;
            if (i < 300) s += __ldg(&((const float4*)W2)[i]).y;
            if (s != s) g_sink = s;                    // keep loads; never fires
        }
    }
    __syncthreads();
    if (tid < D4) {
        float4 t0 = s_acc[0][tid], t1 = s_acc[1][tid];
        float4 t2 = s_acc[2][tid], t3 = s_acc[3][tid];
        g_part1[(4 * tid + 0) * NB + b] = (t0.x + t1.x) + (t2.x + t3.x);
        g_part1[(4 * tid + 1) * NB + b] = (t0.y + t1.y) + (t2.y + t3.y);
        g_part1[(4 * tid + 2) * NB + b] = (t0.z + t1.z) + (t2.z + t3.z);
        g_part1[(4 * tid + 3) * NB + b] = (t0.w + t1.w) + (t2.w + t3.w);
    }
    gbar(0);

    // ---- Phase B: dense[d] = sum_b part1[d][b]/S. Row d -> block d&127.
    if (w < 3) {
        const int d = w * NB + b;
        if (d < D_SZ) {
            const float* pp = g_part1 + (long)d * NB;
            float v = (pp[lane] + pp[lane + 32]) + (pp[lane + 64] + pp[lane + 96]);
            v = warp_sum(v);
            if (lane == 0) g_dense[d] = v * (1.0f / S_SZ);
        }
    }
    gbar(1);

    // ---- Phase C: mid = W1*dense + b1 (rows spread over all blocks)
    for (int d = tid; d < D_SZ; d += NT) s_v[d] = g_dense[d];
    __syncthreads();
    if (w < 3) {
        const int d = w * NB + b;
        if (d < D_SZ) {
            float p = warp_row_dot((const float4*)(W1 + (long)d * D_SZ), s_v4, lane);
            if (lane == 0) g_mid[d] = p + __ldg(&b1[d]);
        }
    }
    gbar(2);

    // ---- Phase D: t = Wb*mid; block 0 also computes W2*mid
    for (int d = tid; d < D_SZ; d += NT) s_v[d] = g_mid[d];
    __syncthreads();
    if (w < 3) {
        const int d = w * NB + b;
        if (d < D_SZ) {
            float p = warp_row_dot((const float4*)(Wb + (long)d * D_SZ), s_v4, lane);
            if (lane == 0) g_t[d] = p;
        }
    } else if (b == 0 && w >= 4 && w < 4 + C_SZ) {
        const int c = w - 4;
        float p = warp_row_dot((const float4*)(W2 + (long)c * D_SZ), s_v4, lane);
        if (lane == 0) g_w2mid[c] = p;
    }
    gbar(3);

    // ---- Phase E: scores, exps, psum, UNNORMALIZED weighted gather, y = W2.partial
    for (int d = tid; d < D_SZ; d += NT) s_v[d] = g_t[d];
    __syncthreads();
    {
        const float bias = __ldg(bb);
        #pragma unroll
        for (int j = 0; j < 2; j++) {
            const int r = w * 2 + j;
            float p = warp_row_dot(emb4 + (long)s_idx[r] * D4, s_v4, lane);
            if (lane == 0) s_sc[r] = p + bias;
        }
    }
    __syncthreads();
    if (w == 0) {                        // scores tiny -> unshifted exp exact-safe
        float e = expf(s_sc[lane]);
        s_e[lane] = e;
        float ps = warp_sum(e);
        if (lane == 0) g_psum[b] = ps;
    }
    __syncthreads();
    if (tid < D_SZ) {                    // weighted gather, weights = raw e (L2-warm)
        const int c = tid % D4, g = tid / D4;
        float4 acc = make_float4(0.f, 0.f, 0.f, 0.f);
        #pragma unroll
        for (int k = 0; k < 8; k++) {
            const int r = g * 8 + k;
            const float wt = s_e[r];
            float4 v = __ldg(&emb4[(long)s_idx[r] * D4 + c]);
            acc.x = fmaf(wt, v.x, acc.x); acc.y = fmaf(wt, v.y, acc.y);
            acc.z = fmaf(wt, v.z, acc.z); acc.w = fmaf(wt, v.w, acc.w);
        }
        s_acc[g][c] = acc;
    }
    __syncthreads();
    if (tid < D4) {                      // combine 4 row-groups (s_v(t) done)
        float4 t0 = s_acc[0][tid], t1 = s_acc[1][tid];
        float4 t2 = s_acc[2][tid], t3 = s_acc[3][tid];
        s_v4[tid] = make_float4((t0.x + t1.x) + (t2.x + t3.x),
                                (t0.y + t1.y) + (t2.y + t3.y),
                                (t0.z + t1.z) + (t2.z + t3.z),
                                (t0.w + t1.w) + (t2.w + t3.w));
    }
    __syncthreads();
    if (w < C_SZ) {                      // y_b[c] = W2[c,:] . block_partial
        float p = warp_row_dot((const float4*)(W2 + (long)w * D_SZ), s_v4, lane);
        if (lane == 0) g_y[w * NB + b] = p;
    }
    gbar(4);

    // ---- Phase F: total (redundant, identical order), rewards, logits
    if (w == 0) {
        float v = (g_psum[lane] + g_psum[lane + 32])
                + (g_psum[lane + 64] + g_psum[lane + 96]);
        v = warp_sum(v);
        if (lane == 0) s_bc = 1.0f / v;
    }
    __syncthreads();
    const float inv = s_bc;
    if (tid < RPB)
        out[C_SZ + b * RPB + tid] = s_e[tid] * inv;

    if (b == 0 && w < C_SZ) {
        const float* yy = g_y + (long)w * NB;
        float v = (yy[lane] + yy[lane + 32]) + (yy[lane + 64] + yy[lane + 96]);
        v = warp_sum(v);
        if (lane == 0)
            out[w] = g_w2mid[w] + v * inv * (1.0f / S_SZ) + __ldg(&b2[w]);
    }
}

// ---------------------------------------------------------------------------
extern "C" void kernel_launch(void* const* d_in, const int* in_sizes, int n_in,
                              void* d_out, int out_size)
{
    const int*   x   = (const int*)  d_in[0];
    const float* emb = (const float*)d_in[1];
    const float* W1  = (const float*)d_in[2];
    const float* b1  = (const float*)d_in[3];
    const float* Wb  = (const float*)d_in[4];
    const float* bb  = (const float*)d_in[5];
    const float* W2  = (const float*)d_in[6];
    const float* b2  = (const float*)d_in[7];
    float* out = (float*)d_out;   // out[0:4] = output, out[4:4100] = reward

    fused<<<NB, NT>>>(x, emb, W1, b1, Wb, bb, W2, b2, out);
}